// round 5
// baseline (speedup 1.0000x reference)
#include <cuda_runtime.h>
#include <math.h>

// Problem constants
#define NR   2048
#define L    128
#define FGV  2.0f

// Tiling
#define RPB      8                   // rows per chunk
#define THREADS  128
#define WPB      4                   // warps per block
#define BPC      10                  // blocks per chunk (40 warps of work)
#define NCHUNKS  (NR / RPB)          // 256
#define GRID     (BPC * NCHUNKS)     // 2560
#define PADF     128                 // overread pad (j can reach 151 on last row)

// Per-block partials (overwritten every launch -> deterministic)
__device__ float    g_part[GRID];
__device__ float    g_fpart[GRID];
__device__ unsigned g_ctr = 0;       // wraps to 0 via atomicInc every launch

// ---- f32x2 packed helpers (sm_103a) ----
typedef unsigned long long u64;
__device__ __forceinline__ u64 pk2(float lo, float hi) {
    u64 r; asm("mov.b64 %0,{%1,%2};" : "=l"(r) : "f"(lo), "f"(hi)); return r;
}
__device__ __forceinline__ void upk2(u64 v, float& lo, float& hi) {
    asm("mov.b64 {%0,%1},%2;" : "=f"(lo), "=f"(hi) : "l"(v));
}
__device__ __forceinline__ u64 mul2(u64 a, u64 b) {
    u64 r; asm("mul.rn.f32x2 %0,%1,%2;" : "=l"(r) : "l"(a), "l"(b)); return r;
}
__device__ __forceinline__ u64 fma2(u64 a, u64 b, u64 c) {
    u64 r; asm("fma.rn.f32x2 %0,%1,%2,%3;" : "=l"(r) : "l"(a), "l"(b), "l"(c)); return r;
}
__device__ __forceinline__ u64 add2(u64 a, u64 b) {
    u64 r; asm("add.rn.f32x2 %0,%1,%2;" : "=l"(r) : "l"(a), "l"(b)); return r;
}
#define ABSMASK2 0x7fffffff7fffffffULL

__global__ __launch_bounds__(THREADS) void loss_k(
        const float* __restrict__ y_true,
        const float* __restrict__ y_pred,
        const float* __restrict__ y_diff,
        const float* __restrict__ wts,
        float* __restrict__ out)
{
    __shared__ float es[RPB * L + PADF];    // e = f * d
    __shared__ float fsm[RPB * L + PADF];   // f
    __shared__ float redp[WPB];
    __shared__ float redf[WPB];
    __shared__ bool  s_last;

    const int tid  = threadIdx.x;
    const int bx   = blockIdx.x;
    const int nch  = bx / BPC;            // row chunk
    const int bic  = bx - nch * BPC;      // block-in-chunk 0..9
    const int n0   = nch * RPB;
    const int lane = tid & 31;
    const int wid  = tid >> 5;

    // ---- diag weights (k==0 column of both p-planes), one block per chunk ----
    float w0d[4], w1d[4];
    const int c4 = tid & 31;              // column float4-group (THREADS%32==0)
    if (bic == 0) {
#pragma unroll
        for (int s = 0; s < 4; s++) {
            const int c = 4 * c4 + s;
            w0d[s] = wts[c * L];
            w1d[s] = wts[L * L + c * L];
        }
    }

    // ---- stage e, f into smem; fold diagonal term + f-sum (bic==0 only) ----
    float floc  = 0.0f;
    float dpart = 0.0f;
    {
        const float4* yt4 = (const float4*)y_true + (size_t)n0 * (L / 4);
        const float4* yp4 = (const float4*)y_pred + (size_t)n0 * (L / 4);
        const float4* yd4 = (const float4*)y_diff + (size_t)n0 * (L / 4);
#pragma unroll
        for (int it = 0; it < RPB * L / 4 / THREADS; it++) {
            const int idx = tid + it * THREADS;
            const float4 t = yt4[idx];
            const float4 p = yp4[idx];
            const float4 q = yd4[idx];
            float e[4], f[4];
            e[0] = t.x - p.x; e[1] = t.y - p.y; e[2] = t.z - p.z; e[3] = t.w - p.w;
            f[0] = (fabsf(q.x) > FGV) ? 0.0f : 1.0f;
            f[1] = (fabsf(q.y) > FGV) ? 0.0f : 1.0f;
            f[2] = (fabsf(q.z) > FGV) ? 0.0f : 1.0f;
            f[3] = (fabsf(q.w) > FGV) ? 0.0f : 1.0f;
#pragma unroll
            for (int s = 0; s < 4; s++) {
                e[s] *= f[s];
                if (bic == 0) {
                    floc  += f[s];
                    dpart += fabsf(e[s]) * w0d[s] + e[s] * e[s] * w1d[s];
                }
            }
            float4 e4, f4;
            e4.x = e[0]; e4.y = e[1]; e4.z = e[2]; e4.w = e[3];
            f4.x = f[0]; f4.y = f[1]; f4.z = f[2]; f4.w = f[3];
            ((float4*)es)[idx]  = e4;
            ((float4*)fsm)[idx] = f4;
        }
    }
    if (tid < PADF) { es[RPB * L + tid] = 0.0f; fsm[RPB * L + tid] = 0.0f; }
    __syncthreads();

    // ---- warp -> (8-wide i-band a, j-quadrant wq); 40 warps per chunk ----
    const int gw = bic * WPB + wid;       // 0..39
    int a, wq;
    if (gw < 16)      { a = gw >> 2;               wq = gw & 3; }
    else if (gw < 28) { a = 4  + (gw - 16) / 3;    wq = (gw - 16) % 3; }
    else if (gw < 36) { a = 8  + ((gw - 28) >> 1); wq = (gw - 28) & 1; }
    else              { a = 12 + (gw - 36);        wq = 0; }
    const int i0 = 8 * a;                 // 32B-aligned i base
    const int j  = i0 + 32 * wq + lane;   // this lane's j (>= L slots masked later)

    // ---- hot loop: f32x2 pairs; |e_i f_j - e_j f_i| = f_i f_j |d_i - d_j| ----
    u64 S1[4] = {0, 0, 0, 0}, S2[4] = {0, 0, 0, 0};
#pragma unroll
    for (int r = 0; r < RPB; r++) {
        const float* er = es  + r * L;
        const float* fr = fsm + r * L;
        const float  ej = er[j];
        const float  fj = fr[j];
        const float4 ea = *(const float4*)(er + i0);
        const float4 eb = *(const float4*)(er + i0 + 4);
        const float4 fa = *(const float4*)(fr + i0);
        const float4 fb = *(const float4*)(fr + i0 + 4);
        const float nej = -ej;
        const u64 nej2 = pk2(nej, nej);
        const u64 fj2  = pk2(fj, fj);
        const u64 ei2[4] = { pk2(ea.x, ea.y), pk2(ea.z, ea.w),
                             pk2(eb.x, eb.y), pk2(eb.z, eb.w) };
        const u64 fi2[4] = { pk2(fa.x, fa.y), pk2(fa.z, fa.w),
                             pk2(fb.x, fb.y), pk2(fb.z, fb.w) };
#pragma unroll
        for (int p = 0; p < 4; p++) {
            const u64 t = mul2(nej2, fi2[p]);       // -e_j * f_i   (pair)
            const u64 u = fma2(ei2[p], fj2, t);     // e_i f_j - e_j f_i
            S1[p] = add2(S1[p], u & ABSMASK2);      // p = 1 (abs on ALU pipe)
            S2[p] = fma2(u, u, S2[p]);              // p = 2
        }
    }

    // ---- epilogue: unpack, apply weights once, mask invalid slots ----
    float S1f[8], S2f[8];
#pragma unroll
    for (int p = 0; p < 4; p++) {
        upk2(S1[p], S1f[2 * p], S1f[2 * p + 1]);
        upk2(S2[p], S2f[2 * p], S2f[2 * p + 1]);
    }
    float part = (bic == 0) ? dpart : 0.0f;
#pragma unroll
    for (int s = 0; s < 8; s++) {
        const int  i     = i0 + s;
        const int  k     = j - i;                 // k>=1 live; k==0 in staging
        const bool valid = (k >= 1) && (j < L);
        const int  kc    = min(max(k, 1), L - 1);
        const float w0 = wts[i * L + kc];
        const float w1 = wts[L * L + i * L + kc];
        part += (valid ? 1.0f : 0.0f) * (w0 * S1f[s] + w1 * S2f[s]);
    }

    // ---- block reduction -> per-block partial ----
#pragma unroll
    for (int o = 16; o > 0; o >>= 1) {
        part += __shfl_xor_sync(0xffffffffu, part, o);
        floc += __shfl_xor_sync(0xffffffffu, floc, o);
    }
    if (lane == 0) { redp[wid] = part; redf[wid] = floc; }
    __syncthreads();
    if (tid == 0) {
        float p = 0.0f, ff = 0.0f;
#pragma unroll
        for (int w = 0; w < WPB; w++) { p += redp[w]; ff += redf[w]; }
        g_part[bx]  = p;
        g_fpart[bx] = ff;
        __threadfence();
        const unsigned old = atomicInc(&g_ctr, GRID - 1);   // wraps each launch
        s_last = (old == GRID - 1);
    }
    __syncthreads();

    // ---- last block finalizes ----
    if (s_last) {
        __threadfence();
        double lp = 0.0;
        float  fp = 0.0f;
        for (int idx = tid; idx < GRID; idx += THREADS) {
            lp += (double)g_part[idx];
            fp += g_fpart[idx];
        }
#pragma unroll
        for (int o = 16; o > 0; o >>= 1) {
            lp += __shfl_xor_sync(0xffffffffu, lp, o);
            fp += __shfl_xor_sync(0xffffffffu, fp, o);
        }
        __shared__ double dred[WPB];
        __shared__ float  fred[WPB];
        if (lane == 0) { dred[wid] = lp; fred[wid] = fp; }
        __syncthreads();
        if (tid == 0) {
            double lt = 0.0; float ft = 0.0f;
#pragma unroll
            for (int w = 0; w < WPB; w++) { lt += dred[w]; ft += fred[w]; }
            // loss/l/(n*mean(f)) == total / sum(f); f counted once per chunk
            out[0] = (float)(lt / (double)ft);
        }
    }
}

extern "C" void kernel_launch(void* const* d_in, const int* in_sizes, int n_in,
                              void* d_out, int out_size)
{
    const float* y_true  = (const float*)d_in[0];
    const float* y_pred  = (const float*)d_in[1];
    const float* y_diff  = (const float*)d_in[2];
    const float* weights = (const float*)d_in[3];
    loss_k<<<GRID, THREADS>>>(y_true, y_pred, y_diff, weights, (float*)d_out);
}

// round 6
// speedup vs baseline: 1.5496x; 1.5496x over previous
#include <cuda_runtime.h>
#include <math.h>

// Problem constants
#define NR   2048
#define L    128
#define FGV  2.0f

// Tiling
#define RPB      16                  // rows per chunk
#define THREADS  256
#define WPB      8                   // warps per block
#define BPC      5                   // blocks per chunk (40 warps of work)
#define NCHUNKS  (NR / RPB)          // 128
#define GRID     (BPC * NCHUNKS)     // 640
#define PADF     32                  // overread pad (j reaches 151 on last row)

// Per-block partials (overwritten every launch -> deterministic)
__device__ float    g_part[GRID];
__device__ float    g_fpart[GRID];
__device__ unsigned g_ctr = 0;       // wraps to 0 via atomicInc every launch

// ---- f32x2 packed helpers (sm_103a) ----
typedef unsigned long long u64;
__device__ __forceinline__ u64 pk2(float lo, float hi) {
    u64 r; asm("mov.b64 %0,{%1,%2};" : "=l"(r) : "f"(lo), "f"(hi)); return r;
}
__device__ __forceinline__ void upk2(u64 v, float& lo, float& hi) {
    asm("mov.b64 {%0,%1},%2;" : "=f"(lo), "=f"(hi) : "l"(v));
}
__device__ __forceinline__ u64 mul2(u64 a, u64 b) {
    u64 r; asm("mul.rn.f32x2 %0,%1,%2;" : "=l"(r) : "l"(a), "l"(b)); return r;
}
__device__ __forceinline__ u64 fma2(u64 a, u64 b, u64 c) {
    u64 r; asm("fma.rn.f32x2 %0,%1,%2,%3;" : "=l"(r) : "l"(a), "l"(b), "l"(c)); return r;
}
__device__ __forceinline__ u64 add2(u64 a, u64 b) {
    u64 r; asm("add.rn.f32x2 %0,%1,%2;" : "=l"(r) : "l"(a), "l"(b)); return r;
}
#define ABSMASK2 0x7fffffff7fffffffULL

__global__ __launch_bounds__(THREADS) void loss_k(
        const float* __restrict__ y_true,
        const float* __restrict__ y_pred,
        const float* __restrict__ y_diff,
        const float* __restrict__ wts,
        float* __restrict__ out)
{
    __shared__ float es[RPB * L + PADF];    // e = f * d  (separate arrays: u64
    __shared__ float fsm[RPB * L + PADF];   //  pairs load pre-packed, no movs)
    __shared__ float redp[WPB];
    __shared__ float redf[WPB];
    __shared__ bool  s_last;

    const int tid  = threadIdx.x;
    const int bx   = blockIdx.x;
    const int nch  = bx / BPC;            // row chunk
    const int bic  = bx - nch * BPC;      // block-in-chunk 0..4
    const int n0   = nch * RPB;
    const int lane = tid & 31;
    const int wid  = tid >> 5;

    // ---- diag weights (k==0 column of both p-planes), one block per chunk ----
    float w0d[4], w1d[4];
    const int c4 = tid & 31;              // column float4-group (stable per thread)
    if (bic == 0) {
#pragma unroll
        for (int s = 0; s < 4; s++) {
            const int c = 4 * c4 + s;
            w0d[s] = wts[c * L];
            w1d[s] = wts[L * L + c * L];
        }
    }

    // ---- stage e, f into smem; fold diagonal term + f-sum (bic==0 only) ----
    float floc  = 0.0f;
    float dpart = 0.0f;
    {
        const float4* yt4 = (const float4*)y_true + (size_t)n0 * (L / 4);
        const float4* yp4 = (const float4*)y_pred + (size_t)n0 * (L / 4);
        const float4* yd4 = (const float4*)y_diff + (size_t)n0 * (L / 4);
#pragma unroll
        for (int it = 0; it < RPB * L / 4 / THREADS; it++) {
            const int idx = tid + it * THREADS;
            const float4 t = yt4[idx];
            const float4 p = yp4[idx];
            const float4 q = yd4[idx];
            float e[4], f[4];
            e[0] = t.x - p.x; e[1] = t.y - p.y; e[2] = t.z - p.z; e[3] = t.w - p.w;
            f[0] = (fabsf(q.x) > FGV) ? 0.0f : 1.0f;
            f[1] = (fabsf(q.y) > FGV) ? 0.0f : 1.0f;
            f[2] = (fabsf(q.z) > FGV) ? 0.0f : 1.0f;
            f[3] = (fabsf(q.w) > FGV) ? 0.0f : 1.0f;
#pragma unroll
            for (int s = 0; s < 4; s++) {
                e[s] *= f[s];
                if (bic == 0) {
                    floc  += f[s];
                    dpart += fabsf(e[s]) * w0d[s] + e[s] * e[s] * w1d[s];
                }
            }
            float4 e4, f4;
            e4.x = e[0]; e4.y = e[1]; e4.z = e[2]; e4.w = e[3];
            f4.x = f[0]; f4.y = f[1]; f4.z = f[2]; f4.w = f[3];
            ((float4*)es)[idx]  = e4;
            ((float4*)fsm)[idx] = f4;
        }
    }
    if (tid < PADF) { es[RPB * L + tid] = 0.0f; fsm[RPB * L + tid] = 0.0f; }
    __syncthreads();

    // ---- warp -> (8-wide i-band a, j-quadrant wq); 40 warps per chunk ----
    const int gw = bic * WPB + wid;       // 0..39
    int a, wq;
    if (gw < 16)      { a = gw >> 2;               wq = gw & 3; }
    else if (gw < 28) { a = 4  + (gw - 16) / 3;    wq = (gw - 16) % 3; }
    else if (gw < 36) { a = 8  + ((gw - 28) >> 1); wq = (gw - 28) & 1; }
    else              { a = 12 + (gw - 36);        wq = 0; }
    const int i0 = 8 * a;                 // 32B-aligned i base
    const int j  = i0 + 32 * wq + lane;   // this lane's j (>= L slots masked)

    // ---- hot loop: f32x2 pairs, packs loaded pre-paired from smem ----
    u64 S1[4] = {0, 0, 0, 0}, S2[4] = {0, 0, 0, 0};
    const float* er = es  + j;
    const float* fr = fsm + j;
    const ulonglong2* ei = (const ulonglong2*)(es  + i0);   // 32B aligned
    const ulonglong2* fi = (const ulonglong2*)(fsm + i0);
#pragma unroll
    for (int r = 0; r < RPB; r++) {
        const float ej = er[r * L];
        const float fj = fr[r * L];
        const ulonglong2 ea = ei[r * (L / 4)];      // (e0,e1),(e2,e3) packed
        const ulonglong2 eb = ei[r * (L / 4) + 1];  // (e4,e5),(e6,e7)
        const ulonglong2 fa = fi[r * (L / 4)];
        const ulonglong2 fb = fi[r * (L / 4) + 1];
        const float nej = -ej;
        const u64 nej2 = pk2(nej, nej);
        const u64 fj2  = pk2(fj, fj);
        const u64 ei2[4] = { ea.x, ea.y, eb.x, eb.y };
        const u64 fi2[4] = { fa.x, fa.y, fb.x, fb.y };
#pragma unroll
        for (int p = 0; p < 4; p++) {
            const u64 t = mul2(nej2, fi2[p]);       // -e_j * f_i   (pair)
            const u64 u = fma2(ei2[p], fj2, t);     // e_i f_j - e_j f_i
            S1[p] = add2(S1[p], u & ABSMASK2);      // p = 1 (abs on ALU pipe)
            S2[p] = fma2(u, u, S2[p]);              // p = 2 (yf^2 = yf)
        }
    }

    // ---- epilogue: unpack, apply weights once, mask invalid slots ----
    float S1f[8], S2f[8];
#pragma unroll
    for (int p = 0; p < 4; p++) {
        upk2(S1[p], S1f[2 * p], S1f[2 * p + 1]);
        upk2(S2[p], S2f[2 * p], S2f[2 * p + 1]);
    }
    float part = (bic == 0) ? dpart : 0.0f;
#pragma unroll
    for (int s = 0; s < 8; s++) {
        const int  i     = i0 + s;
        const int  k     = j - i;                 // k>=1 live; k==0 in staging
        const bool valid = (k >= 1) && (j < L);
        const int  kc    = min(max(k, 1), L - 1);
        const float w0 = wts[i * L + kc];
        const float w1 = wts[L * L + i * L + kc];
        part += (valid ? 1.0f : 0.0f) * (w0 * S1f[s] + w1 * S2f[s]);
    }

    // ---- block reduction -> per-block partial ----
#pragma unroll
    for (int o = 16; o > 0; o >>= 1) {
        part += __shfl_xor_sync(0xffffffffu, part, o);
        floc += __shfl_xor_sync(0xffffffffu, floc, o);
    }
    if (lane == 0) { redp[wid] = part; redf[wid] = floc; }
    __syncthreads();
    if (tid == 0) {
        float p = 0.0f, ff = 0.0f;
#pragma unroll
        for (int w = 0; w < WPB; w++) { p += redp[w]; ff += redf[w]; }
        g_part[bx]  = p;
        g_fpart[bx] = ff;
        __threadfence();
        const unsigned old = atomicInc(&g_ctr, GRID - 1);   // wraps each launch
        s_last = (old == GRID - 1);
    }
    __syncthreads();

    // ---- last block finalizes ----
    if (s_last) {
        __threadfence();
        double lp = 0.0;
        float  fp = 0.0f;
        for (int idx = tid; idx < GRID; idx += THREADS) {
            lp += (double)g_part[idx];
            fp += g_fpart[idx];
        }
#pragma unroll
        for (int o = 16; o > 0; o >>= 1) {
            lp += __shfl_xor_sync(0xffffffffu, lp, o);
            fp += __shfl_xor_sync(0xffffffffu, fp, o);
        }
        __shared__ double dred[WPB];
        __shared__ float  fred[WPB];
        if (lane == 0) { dred[wid] = lp; fred[wid] = fp; }
        __syncthreads();
        if (tid == 0) {
            double lt = 0.0; float ft = 0.0f;
#pragma unroll
            for (int w = 0; w < WPB; w++) { lt += dred[w]; ft += fred[w]; }
            // loss/l/(n*mean(f)) == total / sum(f); f counted once per chunk
            out[0] = (float)(lt / (double)ft);
        }
    }
}

extern "C" void kernel_launch(void* const* d_in, const int* in_sizes, int n_in,
                              void* d_out, int out_size)
{
    const float* y_true  = (const float*)d_in[0];
    const float* y_pred  = (const float*)d_in[1];
    const float* y_diff  = (const float*)d_in[2];
    const float* weights = (const float*)d_in[3];
    loss_k<<<GRID, THREADS>>>(y_true, y_pred, y_diff, weights, (float*)d_out);
}